// round 3
// baseline (speedup 1.0000x reference)
#include <cuda_runtime.h>
#include <cstdint>

#define N_IMG 512
#define N_NEO 510
#define NCLS 32
#define NHID 64
#define CST 96
#define ODIM 98
#define ITERS 50
#define NACT 510
#define CELLS (N_NEO*N_NEO)      // 260100
#define PLANE (N_IMG*N_IMG)      // 262144
#define BX 32
#define BY 8

// Persistent scratch (static device globals — allowed; no runtime allocation)
__device__ float    g_proj[2][9*PLANE];   // cumulative projections, ping-pong, zero borders
__device__ float4   g_class4[8*CELLS];    // class accumulators, SoA-of-float4
__device__ unsigned g_perc[CELLS];        // packed (px | py<<16)

__device__ __forceinline__ float sig_from_t(float t) {
    // t = -pre * log2(e); returns sigmoid(pre) = 1/(1+2^t)
    float e; asm("ex2.approx.f32 %0, %1;" : "=f"(e) : "f"(t));
    float d = 1.0f + e;
    float r; asm("rcp.approx.f32 %0, %1;" : "=f"(r) : "f"(d));
    return r;
}

__global__ void prep_kernel() {
    long stride = (long)gridDim.x * blockDim.x;
    long i0 = (long)blockIdx.x * blockDim.x + threadIdx.x;
    float* pr = (float*)g_proj;
    const long total = 2L * 9 * PLANE;
    for (long k = i0; k < total; k += stride) pr[k] = 0.0f;
    for (long k = i0; k < CELLS; k += stride) {
        int n = (int)(k / N_NEO);
        int m = (int)(k - (long)n * N_NEO);
        g_perc[k] = (unsigned)n | ((unsigned)m << 16);
    }
}

__global__ __launch_bounds__(BX*BY) void step_kernel(
    const float* __restrict__ img,
    const float* __restrict__ comms_w,
    const float* __restrict__ comms_b,
    const float* __restrict__ perc_w,
    const float* __restrict__ perc_b,
    const float* __restrict__ out_w,
    const float* __restrict__ out_b,
    int t)
{
    __shared__ float4 sWP[ODIM];     // (-w0*L2E, -w1*L2E, -b*L2E, 0)
    __shared__ float4 sCWa[CST];     // comms_w transposed, offs 0..3
    __shared__ float4 sCWb[CST];     // offs 4..7
    __shared__ float  sCWc[CST];     // off 8
    __shared__ float  sPW[9];

    const int tid = threadIdx.y*BX + threadIdx.x;
    const float L2E = 1.4426950408889634f;

    for (int k = tid; k < ODIM; k += BX*BY) {
        float w0 = out_w[k];
        float w1 = out_w[ODIM + k];
        float b  = out_b[k];
        sWP[k] = make_float4(-w0*L2E, -w1*L2E, -b*L2E, 0.0f);
    }
    for (int k = tid; k < CST; k += BX*BY) {
        sCWa[k] = make_float4(comms_w[0*CST+k], comms_w[1*CST+k],
                              comms_w[2*CST+k], comms_w[3*CST+k]);
        sCWb[k] = make_float4(comms_w[4*CST+k], comms_w[5*CST+k],
                              comms_w[6*CST+k], comms_w[7*CST+k]);
        sCWc[k] = comms_w[8*CST+k];
    }
    if (tid < 9) sPW[tid] = perc_w[tid];
    __syncthreads();

    const int m = blockIdx.x*BX + threadIdx.x;
    const int n = blockIdx.y*BY + threadIdx.y;
    if (n >= N_NEO || m >= N_NEO) return;
    const int idx = n*N_NEO + m;

    const float* __restrict__ src = g_proj[t & 1];
    float* __restrict__       dst = g_proj[(t & 1) ^ 1];

    // ---- perception (uses perc BEFORE update) ----
    unsigned pc = g_perc[idx];
    int px = (int)(pc & 0xFFFFu);
    int py = (int)(pc >> 16);
    float p = perc_b[0];
    #pragma unroll
    for (int i = 0; i < 3; i++) {
        #pragma unroll
        for (int j = 0; j < 3; j++)
            p = fmaf(img[(px+i)*N_IMG + (py+j)], sPW[i*3+j], p);
    }

    // ---- comms from neighbors' cumulative projections (state BEFORE update) ----
    float c = comms_b[0];
    #pragma unroll
    for (int i = 0; i < 3; i++) {
        #pragma unroll
        for (int j = 0; j < 3; j++) {
            int o = i*3 + j;
            c += src[o*PLANE + (n+i)*N_IMG + (m+j)];
        }
    }

    // ---- class accumulators (prefetch early) ----
    float cls[NCLS];
    if (t != 0) {
        #pragma unroll
        for (int g = 0; g < 8; g++) {
            float4 v = g_class4[g*CELLS + idx];
            cls[4*g+0] = v.x; cls[4*g+1] = v.y; cls[4*g+2] = v.z; cls[4*g+3] = v.w;
        }
    } else {
        #pragma unroll
        for (int k = 0; k < NCLS; k++) cls[k] = 0.0f;
    }

    float inc[9];
    #pragma unroll
    for (int o = 0; o < 9; o++) inc[o] = 0.0f;

    // ---- hidden channels 0..63: sigmoid + projection update ----
    #pragma unroll 4
    for (int ch = 0; ch < NHID; ch++) {
        float4 wp = sWP[ch];
        float tt = fmaf(c, wp.x, fmaf(p, wp.y, wp.z));
        float s  = sig_from_t(tt);
        float4 a  = sCWa[ch];
        float4 b2 = sCWb[ch];
        inc[0] = fmaf(s, a.x,  inc[0]);
        inc[1] = fmaf(s, a.y,  inc[1]);
        inc[2] = fmaf(s, a.z,  inc[2]);
        inc[3] = fmaf(s, a.w,  inc[3]);
        inc[4] = fmaf(s, b2.x, inc[4]);
        inc[5] = fmaf(s, b2.y, inc[5]);
        inc[6] = fmaf(s, b2.z, inc[6]);
        inc[7] = fmaf(s, b2.w, inc[7]);
        inc[8] = fmaf(s, sCWc[ch], inc[8]);
    }

    // ---- class channels 64..95: sigmoid + projection update + class accumulate ----
    #pragma unroll
    for (int q = 0; q < NCLS; q++) {
        int ch = NHID + q;
        float4 wp = sWP[ch];
        float tt = fmaf(c, wp.x, fmaf(p, wp.y, wp.z));
        float s  = sig_from_t(tt);
        cls[q] += s;
        float4 a  = sCWa[ch];
        float4 b2 = sCWb[ch];
        inc[0] = fmaf(s, a.x,  inc[0]);
        inc[1] = fmaf(s, a.y,  inc[1]);
        inc[2] = fmaf(s, a.z,  inc[2]);
        inc[3] = fmaf(s, a.w,  inc[3]);
        inc[4] = fmaf(s, b2.x, inc[4]);
        inc[5] = fmaf(s, b2.y, inc[5]);
        inc[6] = fmaf(s, b2.z, inc[6]);
        inc[7] = fmaf(s, b2.w, inc[7]);
        inc[8] = fmaf(s, sCWc[ch], inc[8]);
    }

    // ---- action channels 96, 97 -> perc delta ----
    {
        float4 wpA = sWP[CST + 0];
        float4 wpB = sWP[CST + 1];
        float sA = sig_from_t(fmaf(c, wpA.x, fmaf(p, wpA.y, wpA.z)));
        float sB = sig_from_t(fmaf(c, wpB.x, fmaf(p, wpB.y, wpB.z)));
        const float TH = 0.0007f;
        // sigmoid > 0 > -TH so delta in {0, 1}
        int dx = (sA > TH) ? 1 : 0;
        int dy = (sB > TH) ? 1 : 0;
        px = min(max(px + dx, 0), NACT - 1);
        py = min(max(py + dy, 0), NACT - 1);
        g_perc[idx] = (unsigned)px | ((unsigned)py << 16);
    }

    // ---- write updated cumulative projections (own prev + inc) ----
    #pragma unroll
    for (int o = 0; o < 9; o++) {
        int pos = o*PLANE + (n+1)*N_IMG + (m+1);
        dst[pos] = src[pos] + inc[o];
    }

    // ---- write class accumulators ----
    #pragma unroll
    for (int g = 0; g < 8; g++)
        g_class4[g*CELLS + idx] = make_float4(cls[4*g+0], cls[4*g+1],
                                              cls[4*g+2], cls[4*g+3]);
}

__global__ void out_kernel(float4* __restrict__ out) {
    int idx = blockIdx.x*blockDim.x + threadIdx.x;
    if (idx >= CELLS) return;
    #pragma unroll
    for (int g = 0; g < 8; g++)
        out[idx*8 + g] = g_class4[g*CELLS + idx];
}

extern "C" void kernel_launch(void* const* d_in, const int* in_sizes, int n_in,
                              void* d_out, int out_size) {
    const float* img     = (const float*)d_in[0];
    const float* comms_w = (const float*)d_in[1];
    const float* comms_b = (const float*)d_in[2];
    const float* perc_w  = (const float*)d_in[3];
    const float* perc_b  = (const float*)d_in[4];
    const float* out_w   = (const float*)d_in[5];
    const float* out_b   = (const float*)d_in[6];

    prep_kernel<<<2048, 256>>>();

    dim3 block(BX, BY);
    dim3 grid((N_NEO + BX - 1)/BX, (N_NEO + BY - 1)/BY);
    for (int t = 0; t < ITERS; t++) {
        step_kernel<<<grid, block>>>(img, comms_w, comms_b, perc_w, perc_b,
                                     out_w, out_b, t);
    }
    out_kernel<<<(CELLS + 255)/256, 256>>>((float4*)d_out);
}

// round 11
// speedup vs baseline: 1.3437x; 1.3437x over previous
#include <cuda_runtime.h>
#include <cstdint>

#define N_IMG 512
#define N_NEO 510
#define NCLS 32
#define NHID 64
#define CST 96
#define ODIM 98
#define ITERS 50
#define NACT 510
#define CELLS (N_NEO*N_NEO)      // 260100
#define PLANE (N_IMG*N_IMG)      // 262144
#define BX 32
#define BY 8

typedef unsigned long long ull;

// Persistent scratch (static device globals — allowed; no runtime allocation)
__device__ float    g_proj[2][9*PLANE];   // cumulative projections, ping-pong, zero borders
__device__ float4   g_class4[8*CELLS];    // class accumulators, SoA-of-float4
__device__ unsigned g_perc[CELLS];        // packed (px | py<<16)

__device__ __forceinline__ ull pk2(float lo, float hi) {
    ull r; asm("mov.b64 %0, {%1, %2};" : "=l"(r) : "f"(lo), "f"(hi)); return r;
}
__device__ __forceinline__ void upk2(float& lo, float& hi, ull v) {
    asm("mov.b64 {%0, %1}, %2;" : "=f"(lo), "=f"(hi) : "l"(v));
}
__device__ __forceinline__ ull fma2(ull a, ull b, ull c) {
    ull d; asm("fma.rn.f32x2 %0, %1, %2, %3;" : "=l"(d) : "l"(a), "l"(b), "l"(c)); return d;
}
__device__ __forceinline__ float ex2f(float t) {
    float e; asm("ex2.approx.f32 %0, %1;" : "=f"(e) : "f"(t)); return e;
}
__device__ __forceinline__ float rcpf(float d) {
    float r; asm("rcp.approx.f32 %0, %1;" : "=f"(r) : "f"(d)); return r;
}

__global__ void prep_kernel() {
    long stride = (long)gridDim.x * blockDim.x;
    long i0 = (long)blockIdx.x * blockDim.x + threadIdx.x;
    float* pr = (float*)g_proj;
    const long total = 2L * 9 * PLANE;
    for (long k = i0; k < total; k += stride) pr[k] = 0.0f;
    for (long k = i0; k < CELLS; k += stride) {
        int n = (int)(k / N_NEO);
        int m = (int)(k - (long)n * N_NEO);
        g_perc[k] = (unsigned)n | ((unsigned)m << 16);
    }
}

// pair body: computes sigmoids (sa, sb) of channels (2q, 2q+1) and accumulates
// their 9-offset projection increments into the packed accumulators.
__device__ __forceinline__ float2 pair_body(
    const float* __restrict__ sPk, int q, ull cc, ull pp,
    ull& inc01, ull& inc23, ull& inc45, ull& inc67, float& inc8)
{
    const ulonglong2* P = (const ulonglong2*)&sPk[24*q];
    ulonglong2 u0 = P[0];  // (w0pair, w1pair)
    ulonglong2 u1 = P[1];  // (bpair, W8pair)
    ull tt = fma2(cc, u0.x, fma2(pp, u0.y, u1.x));
    float ta, tb; upk2(ta, tb, tt);
    float w8a, w8b; upk2(w8a, w8b, u1.y);
    float sa = rcpf(1.0f + ex2f(ta));
    float sb = rcpf(1.0f + ex2f(tb));
    ull saa = pk2(sa, sa);
    ull sbb = pk2(sb, sb);
    ulonglong2 ua0 = P[2], ua1 = P[3], ub0 = P[4], ub1 = P[5];
    inc01 = fma2(saa, ua0.x, inc01);
    inc23 = fma2(saa, ua0.y, inc23);
    inc45 = fma2(saa, ua1.x, inc45);
    inc67 = fma2(saa, ua1.y, inc67);
    inc8  = fmaf(sa, w8a, inc8);
    inc01 = fma2(sbb, ub0.x, inc01);
    inc23 = fma2(sbb, ub0.y, inc23);
    inc45 = fma2(sbb, ub1.x, inc45);
    inc67 = fma2(sbb, ub1.y, inc67);
    inc8  = fmaf(sb, w8b, inc8);
    return make_float2(sa, sb);
}

// Packed smem weights: 48 channel-pairs x 24 floats (96B, 6x LDS.128 per pair):
//  [0..3]  w0a' w0b' w1a' w1b'   (w' = -log2(e) * out_w)
//  [4..7]  ba'  bb'  W8a  W8b
//  [8..15] Wa0..Wa7
//  [16..23] Wb0..Wb7
__global__ __launch_bounds__(BX*BY, 4) void step_kernel(
    const float* __restrict__ img,
    const float* __restrict__ comms_w,
    const float* __restrict__ comms_b,
    const float* __restrict__ perc_w,
    const float* __restrict__ perc_b,
    const float* __restrict__ out_w,
    const float* __restrict__ out_b,
    int t)
{
    __shared__ float sPk[48*24];
    __shared__ float sAct[8];      // w0A' w0B' w1A' w1B' bA' bB' (pad 2)
    __shared__ float sPW[12];      // perc 3x3 weights (+pad)

    const int tid = threadIdx.y*BX + threadIdx.x;
    const float L2E = 1.4426950408889634f;

    for (int q = tid; q < 48; q += BX*BY) {
        int a = 2*q, b = 2*q + 1;
        float* d = &sPk[24*q];
        d[0] = -L2E * out_w[a];
        d[1] = -L2E * out_w[b];
        d[2] = -L2E * out_w[ODIM + a];
        d[3] = -L2E * out_w[ODIM + b];
        d[4] = -L2E * out_b[a];
        d[5] = -L2E * out_b[b];
        d[6] = comms_w[8*CST + a];
        d[7] = comms_w[8*CST + b];
        #pragma unroll
        for (int o = 0; o < 8; o++) {
            d[8 + o]  = comms_w[o*CST + a];
            d[16 + o] = comms_w[o*CST + b];
        }
    }
    if (tid == 48) {
        sAct[0] = -L2E * out_w[CST + 0];
        sAct[1] = -L2E * out_w[CST + 1];
        sAct[2] = -L2E * out_w[ODIM + CST + 0];
        sAct[3] = -L2E * out_w[ODIM + CST + 1];
        sAct[4] = -L2E * out_b[CST + 0];
        sAct[5] = -L2E * out_b[CST + 1];
    }
    if (tid < 9) sPW[tid] = perc_w[tid];
    __syncthreads();

    const int m = blockIdx.x*BX + threadIdx.x;
    const int n = blockIdx.y*BY + threadIdx.y;
    if (n >= N_NEO || m >= N_NEO) return;
    const int idx = n*N_NEO + m;

    const float* __restrict__ src = g_proj[t & 1];
    float* __restrict__       dst = g_proj[(t & 1) ^ 1];

    // ---- perception (uses perc BEFORE update) ----
    unsigned pc = g_perc[idx];
    int px = (int)(pc & 0xFFFFu);
    int py = (int)(pc >> 16);
    float p = perc_b[0];
    #pragma unroll
    for (int i = 0; i < 3; i++) {
        #pragma unroll
        for (int j = 0; j < 3; j++)
            p = fmaf(img[(px+i)*N_IMG + (py+j)], sPW[i*3+j], p);
    }

    // ---- comms from neighbors' cumulative projections (state BEFORE update) ----
    float c = comms_b[0];
    #pragma unroll
    for (int i = 0; i < 3; i++) {
        #pragma unroll
        for (int j = 0; j < 3; j++) {
            int o = i*3 + j;
            c += src[o*PLANE + (n+i)*N_IMG + (m+j)];
        }
    }

    const ull cc = pk2(c, c);
    const ull pp = pk2(p, p);

    ull inc01 = 0, inc23 = 0, inc45 = 0, inc67 = 0;
    float inc8 = 0.0f;

    // ---- hidden channels: pairs 0..31 ----
    #pragma unroll 8
    for (int q = 0; q < 32; q++) {
        pair_body(sPk, q, cc, pp, inc01, inc23, inc45, inc67, inc8);
    }

    // ---- class channels: pairs 32..47, streamed accumulators ----
    #pragma unroll
    for (int g = 0; g < 4; g++) {
        float4 cg0, cg1;
        if (t != 0) {
            cg0 = g_class4[(2*g + 0)*CELLS + idx];
            cg1 = g_class4[(2*g + 1)*CELLS + idx];
        } else {
            cg0 = make_float4(0.f, 0.f, 0.f, 0.f);
            cg1 = make_float4(0.f, 0.f, 0.f, 0.f);
        }
        float2 s0 = pair_body(sPk, 32 + 4*g + 0, cc, pp, inc01, inc23, inc45, inc67, inc8);
        cg0.x += s0.x; cg0.y += s0.y;
        float2 s1 = pair_body(sPk, 32 + 4*g + 1, cc, pp, inc01, inc23, inc45, inc67, inc8);
        cg0.z += s1.x; cg0.w += s1.y;
        float2 s2 = pair_body(sPk, 32 + 4*g + 2, cc, pp, inc01, inc23, inc45, inc67, inc8);
        cg1.x += s2.x; cg1.y += s2.y;
        float2 s3 = pair_body(sPk, 32 + 4*g + 3, cc, pp, inc01, inc23, inc45, inc67, inc8);
        cg1.z += s3.x; cg1.w += s3.y;
        g_class4[(2*g + 0)*CELLS + idx] = cg0;
        g_class4[(2*g + 1)*CELLS + idx] = cg1;
    }

    // ---- action channels 96, 97 -> perc delta ----
    {
        float tA = fmaf(c, sAct[0], fmaf(p, sAct[2], sAct[4]));
        float tB = fmaf(c, sAct[1], fmaf(p, sAct[3], sAct[5]));
        float sA = rcpf(1.0f + ex2f(tA));
        float sB = rcpf(1.0f + ex2f(tB));
        const float TH = 0.0007f;
        // sigmoid > 0 > -TH so delta in {0, 1}
        int dx = (sA > TH) ? 1 : 0;
        int dy = (sB > TH) ? 1 : 0;
        px = min(px + dx, NACT - 1);
        py = min(py + dy, NACT - 1);
        g_perc[idx] = (unsigned)px | ((unsigned)py << 16);
    }

    // ---- write updated cumulative projections (own prev + inc) ----
    {
        float i0, i1, i2, i3, i4, i5, i6, i7;
        upk2(i0, i1, inc01); upk2(i2, i3, inc23);
        upk2(i4, i5, inc45); upk2(i6, i7, inc67);
        float incv[9] = {i0, i1, i2, i3, i4, i5, i6, i7, inc8};
        #pragma unroll
        for (int o = 0; o < 9; o++) {
            int pos = o*PLANE + (n+1)*N_IMG + (m+1);
            dst[pos] = src[pos] + incv[o];
        }
    }
}

__global__ void out_kernel(float4* __restrict__ out) {
    int idx = blockIdx.x*blockDim.x + threadIdx.x;
    if (idx >= CELLS) return;
    #pragma unroll
    for (int g = 0; g < 8; g++)
        out[idx*8 + g] = g_class4[g*CELLS + idx];
}

extern "C" void kernel_launch(void* const* d_in, const int* in_sizes, int n_in,
                              void* d_out, int out_size) {
    const float* img     = (const float*)d_in[0];
    const float* comms_w = (const float*)d_in[1];
    const float* comms_b = (const float*)d_in[2];
    const float* perc_w  = (const float*)d_in[3];
    const float* perc_b  = (const float*)d_in[4];
    const float* out_w   = (const float*)d_in[5];
    const float* out_b   = (const float*)d_in[6];

    prep_kernel<<<2048, 256>>>();

    dim3 block(BX, BY);
    dim3 grid((N_NEO + BX - 1)/BX, (N_NEO + BY - 1)/BY);
    for (int t = 0; t < ITERS; t++) {
        step_kernel<<<grid, block>>>(img, comms_w, comms_b, perc_w, perc_b,
                                     out_w, out_b, t);
    }
    out_kernel<<<(CELLS + 255)/256, 256>>>((float4*)d_out);
}